// round 14
// baseline (speedup 1.0000x reference)
#include <cuda_runtime.h>
#include <math.h>

#define IDIM 128
#define HDIM 1024
#define CDIM 256
#define NIT  4
#define NTOK 2048
#define G    2            // tokens per block (two warps per token)
#define NT   128          // threads per block (4 warps)
#define NBLK (NTOK / G)   // 1024 blocks
#define IGNORE_OUT 10000.0f
#define FULLMASK 0xffffffffu

// pair-local named barrier: 64 threads (two warps of one token), ids 1..2
#define PAIR_BAR(tokid) asm volatile("bar.sync %0, 64;" :: "r"((tokid) + 1) : "memory")

// ---- device scratch (no allocations allowed) ----
__device__ float g_wf[NIT * IDIM * IDIM];  // fused W: [it][d][o], o-contiguous
__device__ float g_bf[NIT * IDIM];         // fused bias: [it][o]
__device__ float g_partS[NBLK];
__device__ int   g_partC[NBLK];
__device__ unsigned int g_ticket;          // zero-init; reset by last block each replay

// ================= prologue: fused-weight GEMM =================
// Wf[it][d][o] = sum_{c<256} w1[it*256+c][d] * w2[o][it*256+c]
// bf[it][o]    = sum_{c<256} b1[it*256+c]    * w2[o][it*256+c] + b2[o]
__global__ __launch_bounds__(256) void gemm_fuse(const float* __restrict__ w1,
                                                 const float* __restrict__ w2,
                                                 const float* __restrict__ b1,
                                                 const float* __restrict__ b2)
{
    __shared__ float As[32][33];   // [c][d_local]
    __shared__ float Bs[32][33];   // [c][o_local]
    const int b  = blockIdx.x;     // 64 blocks: it(4) x dt(4) x ot(4)
    const int it = b >> 4;
    const int dt = (b >> 2) & 3;
    const int ot = b & 3;
    const int tx = threadIdx.x;    // 0..31 (o_local / col)
    const int ty = threadIdx.y;    // 0..7

    float acc[4] = {0.f, 0.f, 0.f, 0.f};
    float bacc = 0.f;

    for (int kc = 0; kc < 8; kc++) {
        #pragma unroll
        for (int i = 0; i < 4; i++) {
            int c = ty + 8 * i;
            As[c][tx] = w1[(it * CDIM + kc * 32 + c) * IDIM + dt * 32 + tx];
            Bs[tx][c] = w2[(ot * 32 + c) * HDIM + it * CDIM + kc * 32 + tx];
        }
        __syncthreads();
        #pragma unroll 8
        for (int c = 0; c < 32; c++) {
            float bv = Bs[c][tx];
            #pragma unroll
            for (int i = 0; i < 4; i++)
                acc[i] = fmaf(As[c][ty + 8 * i], bv, acc[i]);
        }
        if (dt == 0 && ty == 0) {
            #pragma unroll 8
            for (int c = 0; c < 32; c++)
                bacc = fmaf(b1[it * CDIM + kc * 32 + c], Bs[c][tx], bacc);
        }
        __syncthreads();
    }
    #pragma unroll
    for (int i = 0; i < 4; i++)
        g_wf[(it * IDIM + dt * 32 + ty + 8 * i) * IDIM + ot * 32 + tx] = acc[i];
    if (dt == 0 && ty == 0)
        g_bf[it * IDIM + ot * 32 + tx] = bacc + b2[ot * 32 + tx];
}

// ================= fused forward =================
__global__ __launch_bounds__(NT, 8)
void fwd_kernel(const float* __restrict__ x,  const float* __restrict__ y,
                float* __restrict__ out)
{
    __shared__ __align__(16) float sxp[G][384];       // zero-padded x_res (pad 127 each side)
    __shared__ __align__(16) float sy [G][132];       // y_res (padded; 132*4 % 16 == 0)
    __shared__ __align__(16) float sxa[G][132];       // x_attn (padded)
    __shared__ __align__(16) float sP [G][132];       // prefix sums of x^2 (129 used)
    __shared__ __align__(16) float spart[4][G][132];  // MLP d-quarter partials
    __shared__ float s_bv[G][2];                      // per-warp argmax value
    __shared__ int   s_bi[G][2];                      // per-warp argmax index
    __shared__ unsigned char smsk[G][128];            // seq_mask from ORIGINAL y
    __shared__ float redf[4];
    __shared__ int   redi[4];
    __shared__ int   sIsLast;

    const int tid  = threadIdx.x;
    const int blk  = blockIdx.x;
    const int tok0 = blk * G;
    const int lane = tid & 31;
    const int wid  = tid >> 5;        // 4 warps
    const int tok  = wid >> 1;        // token for corr phases (0..1)
    const int sub  = wid & 1;         // corr pass: s in [128*sub, 128*sub+128)
    const int mq   = wid;             // MLP d-quarter 0..3

    // ---- zero sxp pads + load y/mask + count ----
    for (int k = tid; k < G * 384; k += NT) sxp[k / 384][k % 384] = 0.f;

    int cnt = 0;
    #pragma unroll
    for (int q = 0; q < 2; q++) {
        int k = tid + q * NT;                 // 0..255 over (g,d)
        int g = k >> 7, d = k & 127;
        float yv = y[(tok0 + g) * IDIM + d];
        sy[g][d] = yv;
        unsigned char m = (yv == IGNORE_OUT) ? 1 : 0;
        smsk[g][d] = m;
        cnt += 1 - (int)m;
    }
    for (int o = 16; o > 0; o >>= 1) cnt += __shfl_xor_sync(FULLMASK, cnt, o);
    if (lane == 0) redi[wid] = cnt;

    // x_res registers: BOTH warps of a token pair hold identical copies.
    float xr[4];
    #pragma unroll
    for (int k = 0; k < 4; k++)
        xr[k] = x[(tok0 + tok) * IDIM + k * 32 + lane];

    __syncthreads();
    if (tid == 0)
        g_partC[blk] = redi[0] + redi[1] + redi[2] + redi[3];

    // ---- prologue: publish xp + prefix sums for iteration 0 ----
    {
        float* xp = sxp[tok];
        float* Pp = sP[tok];
        if (sub == 1) {
            #pragma unroll
            for (int k = 0; k < 4; k++) xp[127 + k * 32 + lane] = xr[k];
        } else {
            float run = 0.f;
            #pragma unroll
            for (int k = 0; k < 4; k++) {
                float v = xr[k] * xr[k];
                #pragma unroll
                for (int o = 1; o < 32; o <<= 1) {
                    float n = __shfl_up_sync(FULLMASK, v, o);
                    if (lane >= o) v += n;
                }
                Pp[1 + k * 32 + lane] = run + v;
                run += __shfl_sync(FULLMASK, v, 31);
            }
            if (lane == 0) Pp[0] = 0.f;
        }
    }

    float lossAcc = 0.f;

    for (int it = 0; it < NIT; ++it) {
        __syncthreads();   // BAR-TOP: xp/sP publish + prev-iter sy visible

        float* xp = sxp[tok];
        float* Pp = sP[tok];
        float* yp = sy[tok];

        // (1) corr numerators, sliding float4 window.
        //     lane owns shifts s = 4*lane + r + 128*sub  (r = 0..3)
        float a0 = 0.f, a1 = 0.f, a2 = 0.f, a3 = 0.f;
        {
            const float4* xv = (const float4*)(xp) + lane + 32 * sub;
            const float4* yv = (const float4*)(yp);
            float4 cur = xv[0];
            #pragma unroll 8
            for (int t = 0; t < 32; t++) {
                float4 nxt = xv[t + 1];
                float4 y4  = yv[t];
                a0 = fmaf(cur.x, y4.x, a0); a0 = fmaf(cur.y, y4.y, a0);
                a0 = fmaf(cur.z, y4.z, a0); a0 = fmaf(cur.w, y4.w, a0);
                a1 = fmaf(cur.y, y4.x, a1); a1 = fmaf(cur.z, y4.y, a1);
                a1 = fmaf(cur.w, y4.z, a1); a1 = fmaf(nxt.x, y4.w, a1);
                a2 = fmaf(cur.z, y4.x, a2); a2 = fmaf(cur.w, y4.y, a2);
                a2 = fmaf(nxt.x, y4.z, a2); a2 = fmaf(nxt.y, y4.w, a2);
                a3 = fmaf(cur.w, y4.x, a3); a3 = fmaf(nxt.x, y4.y, a3);
                a3 = fmaf(nxt.y, y4.z, a3); a3 = fmaf(nxt.z, y4.w, a3);
                cur = nxt;
            }
        }

        // (2) per-warp sim + first-max argmax over its 128 shifts
        {
            const int s0 = 4 * lane + 128 * sub;
            float num[4] = {a0, a1, a2, a3};
            float bv = -INFINITY; int bi = 0;
            #pragma unroll
            for (int r = 0; r < 4; r++) {
                int s = s0 + r;
                float sim;
                if (s < 255) {
                    int lo = s - 127; if (lo < 0) lo = 0;
                    int hi = s;       if (hi > 127) hi = 127;
                    float dxv = Pp[hi + 1] - Pp[lo];
                    sim = (dxv > 0.f) ? num[r] * rsqrtf(dxv) : 0.f;
                } else sim = -INFINITY;
                if (sim > bv) { bv = sim; bi = s; }   // ascending s keeps first max
            }
            #pragma unroll
            for (int o = 16; o > 0; o >>= 1) {
                float ov = __shfl_xor_sync(FULLMASK, bv, o);
                int   oi = __shfl_xor_sync(FULLMASK, bi, o);
                if (ov > bv || (ov == bv && oi < bi)) { bv = ov; bi = oi; }
            }
            if (lane == 0) { s_bv[tok][sub] = bv; s_bi[tok][sub] = bi; }
        }
        PAIR_BAR(tok);     // pair-local: per-warp bests visible

        // (3) BOTH warps: combine, softmax attention, x_attn (redundant identical)
        int bi;
        {
            float v0 = s_bv[tok][0]; int i0 = s_bi[tok][0];
            float v1 = s_bv[tok][1]; int i1 = s_bi[tok][1];
            bi = (v1 > v0 || (v1 == v0 && i1 < i0)) ? i1 : i0;

            float xa[4], e[4];
            float m = -INFINITY;
            #pragma unroll
            for (int k = 0; k < 4; k++) {
                int d = k * 32 + lane;
                xa[k] = xp[bi + d];                    // kpt[bi][d]
                e[k]  = xa[k] * yp[d];
                m = fmaxf(m, e[k]);
            }
            #pragma unroll
            for (int o = 16; o > 0; o >>= 1) m = fmaxf(m, __shfl_xor_sync(FULLMASK, m, o));
            float se = 0.f;
            #pragma unroll
            for (int k = 0; k < 4; k++) { e[k] = __expf(e[k] - m); se += e[k]; }
            #pragma unroll
            for (int o = 16; o > 0; o >>= 1) se += __shfl_xor_sync(FULLMASK, se, o);
            float inv = 1.f / se;
            #pragma unroll
            for (int k = 0; k < 4; k++) {
                int d = k * 32 + lane;
                sxa[tok][d] = xa[k] * (e[k] * inv);    // both warps write same values
            }
        }
        __syncwarp();       // own sxa writes visible to own cross-lane reads

        // (4) x_res update (reads own-warp sxa copies)
        {
            const int off = bi - 127;
            #pragma unroll
            for (int k = 0; k < 4; k++) {
                int d = k * 32 + lane;
                int q = d - off;
                float xe = (q >= 0 && q < 128) ? sxa[tok][q] : 0.f;
                xr[k] -= xe;
            }
        }
        PAIR_BAR(tok);      // pair-local: xp softmax-reads done before republish

        // (5) republish xp (sub1) + prefix scan (sub0) for NEXT iteration
        if (sub == 1) {
            #pragma unroll
            for (int k = 0; k < 4; k++) xp[127 + k * 32 + lane] = xr[k];
        } else {
            float run = 0.f;
            #pragma unroll
            for (int k = 0; k < 4; k++) {
                float v = xr[k] * xr[k];
                #pragma unroll
                for (int o = 1; o < 32; o <<= 1) {
                    float n = __shfl_up_sync(FULLMASK, v, o);
                    if (lane >= o) v += n;
                }
                Pp[1 + k * 32 + lane] = run + v;
                run += __shfl_sync(FULLMASK, v, 31);
            }
            if (lane == 0) Pp[0] = 0.f;
        }
        __syncthreads();   // BAR-A: sxa visible for fused MLP

        // (6) fused MLP: warp = d-quarter, BOTH tokens per warp (weights loaded once)
        //     lane owns outputs lane*4..+3
        {
            const float*  wp = g_wf + (it * IDIM + mq * 32) * IDIM + lane * 4;
            const float4* h0 = (const float4*)(&sxa[0][mq * 32]);
            const float4* h1 = (const float4*)(&sxa[1][mq * 32]);
            float c00 = 0.f, c01 = 0.f, c02 = 0.f, c03 = 0.f;
            float c10 = 0.f, c11 = 0.f, c12 = 0.f, c13 = 0.f;
            #pragma unroll 4
            for (int k4 = 0; k4 < 8; k4++) {
                float4 ha = h0[k4];                    // broadcast
                float4 hb = h1[k4];                    // broadcast
                const float* w = wp + (k4 * 4) * IDIM;
                float4 w0 = *(const float4*)(w);
                float4 w1v = *(const float4*)(w + IDIM);
                float4 w2v = *(const float4*)(w + 2 * IDIM);
                float4 w3v = *(const float4*)(w + 3 * IDIM);
                c00 = fmaf(w0.x, ha.x, c00); c01 = fmaf(w0.y, ha.x, c01);
                c02 = fmaf(w0.z, ha.x, c02); c03 = fmaf(w0.w, ha.x, c03);
                c10 = fmaf(w0.x, hb.x, c10); c11 = fmaf(w0.y, hb.x, c11);
                c12 = fmaf(w0.z, hb.x, c12); c13 = fmaf(w0.w, hb.x, c13);
                c00 = fmaf(w1v.x, ha.y, c00); c01 = fmaf(w1v.y, ha.y, c01);
                c02 = fmaf(w1v.z, ha.y, c02); c03 = fmaf(w1v.w, ha.y, c03);
                c10 = fmaf(w1v.x, hb.y, c10); c11 = fmaf(w1v.y, hb.y, c11);
                c12 = fmaf(w1v.z, hb.y, c12); c13 = fmaf(w1v.w, hb.y, c13);
                c00 = fmaf(w2v.x, ha.z, c00); c01 = fmaf(w2v.y, ha.z, c01);
                c02 = fmaf(w2v.z, ha.z, c02); c03 = fmaf(w2v.w, ha.z, c03);
                c10 = fmaf(w2v.x, hb.z, c10); c11 = fmaf(w2v.y, hb.z, c11);
                c12 = fmaf(w2v.z, hb.z, c12); c13 = fmaf(w2v.w, hb.z, c13);
                c00 = fmaf(w3v.x, ha.w, c00); c01 = fmaf(w3v.y, ha.w, c01);
                c02 = fmaf(w3v.z, ha.w, c02); c03 = fmaf(w3v.w, ha.w, c03);
                c10 = fmaf(w3v.x, hb.w, c10); c11 = fmaf(w3v.y, hb.w, c11);
                c12 = fmaf(w3v.z, hb.w, c12); c13 = fmaf(w3v.w, hb.w, c13);
            }
            *(float4*)&spart[mq][0][lane * 4] = make_float4(c00, c01, c02, c03);
            *(float4*)&spart[mq][1][lane * 4] = make_float4(c10, c11, c12, c13);
        }
        __syncthreads();   // BAR-C: partials visible

        // (7) warps 0-1: combine quarters (fixed dq order) + loss + y_res update
        if (wid < 2) {
            const int g = wid;
            float4 p0 = *(const float4*)&spart[0][g][lane * 4];
            float4 p1 = *(const float4*)&spart[1][g][lane * 4];
            float4 p2 = *(const float4*)&spart[2][g][lane * 4];
            float4 p3 = *(const float4*)&spart[3][g][lane * 4];
            float4 bfv = *(const float4*)(g_bf + it * IDIM + lane * 4);
            float4 yr  = *(const float4*)&sy[g][lane * 4];
            unsigned int mw = *(const unsigned int*)&smsk[g][lane * 4];
            float ye0 = ((p0.x + p1.x) + (p2.x + p3.x)) + bfv.x;
            float ye1 = ((p0.y + p1.y) + (p2.y + p3.y)) + bfv.y;
            float ye2 = ((p0.z + p1.z) + (p2.z + p3.z)) + bfv.z;
            float ye3 = ((p0.w + p1.w) + (p2.w + p3.w)) + bfv.w;
            float d0 = ye0 - yr.x, d1 = ye1 - yr.y, d2 = ye2 - yr.z, d3 = ye3 - yr.w;
            float k0 = (mw & 0x000000ffu) ? 0.f : 1.f;
            float k1 = (mw & 0x0000ff00u) ? 0.f : 1.f;
            float k2 = (mw & 0x00ff0000u) ? 0.f : 1.f;
            float k3 = (mw & 0xff000000u) ? 0.f : 1.f;
            lossAcc = fmaf(k0 * d0, d0, lossAcc);
            lossAcc = fmaf(k1 * d1, d1, lossAcc);
            lossAcc = fmaf(k2 * d2, d2, lossAcc);
            lossAcc = fmaf(k3 * d3, d3, lossAcc);
            *(float4*)&sy[g][lane * 4] =
                make_float4(yr.x - ye0, yr.y - ye1, yr.z - ye2, yr.w - ye3);
        }
        // loop-top BAR-TOP orders the sy writes before next-iter corr reads
    }

    // ---- deterministic per-block loss reduction ----
    for (int o = 16; o > 0; o >>= 1) lossAcc += __shfl_xor_sync(FULLMASK, lossAcc, o);
    __syncthreads();                 // protect redf reuse
    if (lane == 0) redf[wid] = lossAcc;
    __syncthreads();
    if (tid == 0) {
        g_partS[blk] = (redf[0] + redf[1]) + (redf[2] + redf[3]);
        __threadfence();
        unsigned int t = atomicAdd(&g_ticket, 1u);
        sIsLast = (t == NBLK - 1) ? 1 : 0;
    }
    __syncthreads();

    // ---- last block: fused deterministic finalize ----
    if (sIsLast) {
        __threadfence();
        volatile float* vS = g_partS;
        volatile int*   vC = g_partC;
        float s = 0.f; int c = 0;
        #pragma unroll
        for (int k = 0; k < 8; k++) {        // NBLK = 1024 = 8*NT
            s += vS[tid + k * NT];
            c += vC[tid + k * NT];
        }
        for (int o = 16; o > 0; o >>= 1) {
            s += __shfl_xor_sync(FULLMASK, s, o);
            c += __shfl_xor_sync(FULLMASK, c, o);
        }
        if (lane == 0) { redf[wid] = s; redi[wid] = c; }
        __syncthreads();
        if (tid == 0) {
            float S = (redf[0] + redf[1]) + (redf[2] + redf[3]);
            int   C = redi[0] + redi[1] + redi[2] + redi[3];
            out[0] = S / (4.0f * (float)C);   // mean over NIT of (sum_sq / denom)
            g_ticket = 0;                     // reset for next graph replay
        }
    }
}

extern "C" void kernel_launch(void* const* d_in, const int* in_sizes, int n_in,
                              void* d_out, int out_size)
{
    const float* x  = (const float*)d_in[0];
    const float* y  = (const float*)d_in[1];
    const float* w1 = (const float*)d_in[2];
    const float* b1 = (const float*)d_in[3];
    const float* w2 = (const float*)d_in[4];
    const float* b2 = (const float*)d_in[5];

    gemm_fuse<<<64, dim3(32, 8)>>>(w1, w2, b1, b2);
    fwd_kernel<<<NBLK, NT>>>(x, y, (float*)d_out);
}

// round 15
// speedup vs baseline: 1.1486x; 1.1486x over previous
#include <cuda_runtime.h>
#include <math.h>

#define IDIM 128
#define HDIM 1024
#define CDIM 256
#define NIT  4
#define NTOK 2048
#define G    4            // tokens per block (two warps per token)
#define NT   256          // threads per block
#define NBLK (NTOK / G)   // 512 blocks
#define IGNORE_OUT 10000.0f
#define FULLMASK 0xffffffffu

// pair-local named barrier: 64 threads (two warps of one token), ids 1..4
#define PAIR_BAR(tokid) asm volatile("bar.sync %0, 64;" :: "r"((tokid) + 1) : "memory")

// ---- device scratch (no allocations allowed) ----
__device__ float g_wf[NIT * IDIM * IDIM];  // fused W: [it][d][o], o-contiguous
__device__ float g_bf[NIT * IDIM];         // fused bias: [it][o]
__device__ float g_partS[NBLK];
__device__ int   g_partC[NBLK];
__device__ unsigned int g_ticket;          // zero-init; reset by last block each replay

// ================= prologue: fused-weight GEMM =================
// Wf[it][d][o] = sum_{c<256} w1[it*256+c][d] * w2[o][it*256+c]
// bf[it][o]    = sum_{c<256} b1[it*256+c]    * w2[o][it*256+c] + b2[o]
__global__ __launch_bounds__(256) void gemm_fuse(const float* __restrict__ w1,
                                                 const float* __restrict__ w2,
                                                 const float* __restrict__ b1,
                                                 const float* __restrict__ b2)
{
    __shared__ float As[32][33];   // [c][d_local]
    __shared__ float Bs[32][33];   // [c][o_local]
    const int b  = blockIdx.x;     // 64 blocks: it(4) x dt(4) x ot(4)
    const int it = b >> 4;
    const int dt = (b >> 2) & 3;
    const int ot = b & 3;
    const int tx = threadIdx.x;    // 0..31 (o_local / col)
    const int ty = threadIdx.y;    // 0..7

    float acc[4] = {0.f, 0.f, 0.f, 0.f};
    float bacc = 0.f;

    for (int kc = 0; kc < 8; kc++) {
        #pragma unroll
        for (int i = 0; i < 4; i++) {
            int c = ty + 8 * i;
            As[c][tx] = w1[(it * CDIM + kc * 32 + c) * IDIM + dt * 32 + tx];
            Bs[tx][c] = w2[(ot * 32 + c) * HDIM + it * CDIM + kc * 32 + tx];
        }
        __syncthreads();
        #pragma unroll 8
        for (int c = 0; c < 32; c++) {
            float bv = Bs[c][tx];
            #pragma unroll
            for (int i = 0; i < 4; i++)
                acc[i] = fmaf(As[c][ty + 8 * i], bv, acc[i]);
        }
        if (dt == 0 && ty == 0) {
            #pragma unroll 8
            for (int c = 0; c < 32; c++)
                bacc = fmaf(b1[it * CDIM + kc * 32 + c], Bs[c][tx], bacc);
        }
        __syncthreads();
    }
    #pragma unroll
    for (int i = 0; i < 4; i++)
        g_wf[(it * IDIM + dt * 32 + ty + 8 * i) * IDIM + ot * 32 + tx] = acc[i];
    if (dt == 0 && ty == 0)
        g_bf[it * IDIM + ot * 32 + tx] = bacc + b2[ot * 32 + tx];
}

// ================= fused forward =================
__global__ __launch_bounds__(NT, 4)
void fwd_kernel(const float* __restrict__ x,  const float* __restrict__ y,
                float* __restrict__ out)
{
    __shared__ __align__(16) float sxp[G][384];       // zero-padded x_res (pad 127 each side)
    __shared__ __align__(16) float sy [G][132];       // y_res (padded)
    __shared__ __align__(16) float sxa[G][132];       // x_attn (padded)
    __shared__ __align__(16) float sP [G][132];       // prefix sums of x^2 (129 used)
    __shared__ __align__(16) float spart[4][G][132];  // MLP d-quarter partials
    __shared__ float s_bv[G][2];                      // per-warp argmax value
    __shared__ int   s_bi[G][2];                      // per-warp argmax index
    __shared__ unsigned char smsk[G][128];            // seq_mask from ORIGINAL y
    __shared__ float redf[8];
    __shared__ int   redi[8];
    __shared__ int   sIsLast;

    const int tid  = threadIdx.x;
    const int blk  = blockIdx.x;
    const int tok0 = blk * G;
    const int lane = tid & 31;
    const int wid  = tid >> 5;        // 8 warps
    const int tok  = wid >> 1;        // token for corr phases
    const int sub  = wid & 1;         // corr pass: s in [128*sub, 128*sub+128)

    // ---- zero sxp pads + load y/mask + count ----
    for (int k = tid; k < G * 384; k += NT) sxp[k / 384][k % 384] = 0.f;

    int cnt = 0;
    #pragma unroll
    for (int q = 0; q < 2; q++) {
        int k = tid + q * NT;                 // 0..511 over (g,d)
        int g = k >> 7, d = k & 127;
        float yv = y[(tok0 + g) * IDIM + d];
        sy[g][d] = yv;
        unsigned char m = (yv == IGNORE_OUT) ? 1 : 0;
        smsk[g][d] = m;
        cnt += 1 - (int)m;
    }
    for (int o = 16; o > 0; o >>= 1) cnt += __shfl_xor_sync(FULLMASK, cnt, o);
    if (lane == 0) redi[wid] = cnt;

    // x_res registers: BOTH warps of a token pair hold identical copies.
    float xr[4];
    #pragma unroll
    for (int k = 0; k < 4; k++)
        xr[k] = x[(tok0 + tok) * IDIM + k * 32 + lane];

    __syncthreads();
    if (tid == 0) {
        int c = 0;
        for (int w = 0; w < 8; w++) c += redi[w];
        g_partC[blk] = c;
    }

    // fused-MLP mapping: warp = (d-quarter, token-pair) — weights loaded once per 2 tokens
    const int mq  = wid >> 1;              // d-quarter 0..3
    const int mtp = wid & 1;               // token pair: tokens {2*mtp, 2*mtp+1}

    // ---- prologue: publish xp + prefix sums for iteration 0 ----
    {
        float* xp = sxp[tok];
        float* Pp = sP[tok];
        if (sub == 1) {
            #pragma unroll
            for (int k = 0; k < 4; k++) xp[127 + k * 32 + lane] = xr[k];
        } else {
            float run = 0.f;
            #pragma unroll
            for (int k = 0; k < 4; k++) {
                float v = xr[k] * xr[k];
                #pragma unroll
                for (int o = 1; o < 32; o <<= 1) {
                    float n = __shfl_up_sync(FULLMASK, v, o);
                    if (lane >= o) v += n;
                }
                Pp[1 + k * 32 + lane] = run + v;
                run += __shfl_sync(FULLMASK, v, 31);
            }
            if (lane == 0) Pp[0] = 0.f;
        }
    }

    float lossAcc = 0.f;

    for (int it = 0; it < NIT; ++it) {
        __syncthreads();   // BAR-TOP: xp/sP publish + prev-iter sy visible

        float* xp = sxp[tok];
        float* Pp = sP[tok];
        float* yp = sy[tok];

        // (1) corr numerators, sliding float4 window.
        //     lane owns shifts s = 4*lane + r + 128*sub  (r = 0..3)
        float a0 = 0.f, a1 = 0.f, a2 = 0.f, a3 = 0.f;
        {
            const float4* xv = (const float4*)(xp) + lane + 32 * sub;
            const float4* yv = (const float4*)(yp);
            float4 cur = xv[0];
            #pragma unroll 8
            for (int t = 0; t < 32; t++) {
                float4 nxt = xv[t + 1];
                float4 y4  = yv[t];
                a0 = fmaf(cur.x, y4.x, a0); a0 = fmaf(cur.y, y4.y, a0);
                a0 = fmaf(cur.z, y4.z, a0); a0 = fmaf(cur.w, y4.w, a0);
                a1 = fmaf(cur.y, y4.x, a1); a1 = fmaf(cur.z, y4.y, a1);
                a1 = fmaf(cur.w, y4.z, a1); a1 = fmaf(nxt.x, y4.w, a1);
                a2 = fmaf(cur.z, y4.x, a2); a2 = fmaf(cur.w, y4.y, a2);
                a2 = fmaf(nxt.x, y4.z, a2); a2 = fmaf(nxt.y, y4.w, a2);
                a3 = fmaf(cur.w, y4.x, a3); a3 = fmaf(nxt.x, y4.y, a3);
                a3 = fmaf(nxt.y, y4.z, a3); a3 = fmaf(nxt.z, y4.w, a3);
                cur = nxt;
            }
        }

        // (2) per-warp sim + first-max argmax over its 128 shifts
        {
            const int s0 = 4 * lane + 128 * sub;
            float num[4] = {a0, a1, a2, a3};
            float bv = -INFINITY; int bi = 0;
            #pragma unroll
            for (int r = 0; r < 4; r++) {
                int s = s0 + r;
                float sim;
                if (s < 255) {
                    int lo = s - 127; if (lo < 0) lo = 0;
                    int hi = s;       if (hi > 127) hi = 127;
                    float dxv = Pp[hi + 1] - Pp[lo];
                    sim = (dxv > 0.f) ? num[r] * rsqrtf(dxv) : 0.f;
                } else sim = -INFINITY;
                if (sim > bv) { bv = sim; bi = s; }   // ascending s keeps first max
            }
            #pragma unroll
            for (int o = 16; o > 0; o >>= 1) {
                float ov = __shfl_xor_sync(FULLMASK, bv, o);
                int   oi = __shfl_xor_sync(FULLMASK, bi, o);
                if (ov > bv || (ov == bv && oi < bi)) { bv = ov; bi = oi; }
            }
            if (lane == 0) { s_bv[tok][sub] = bv; s_bi[tok][sub] = bi; }
        }
        PAIR_BAR(tok);     // pair-local: per-warp bests visible

        // (3) BOTH warps: combine, softmax attention, x_attn (redundant identical)
        int bi;
        {
            float v0 = s_bv[tok][0]; int i0 = s_bi[tok][0];
            float v1 = s_bv[tok][1]; int i1 = s_bi[tok][1];
            bi = (v1 > v0 || (v1 == v0 && i1 < i0)) ? i1 : i0;

            float xa[4], e[4];
            float m = -INFINITY;
            #pragma unroll
            for (int k = 0; k < 4; k++) {
                int d = k * 32 + lane;
                xa[k] = xp[bi + d];                    // kpt[bi][d]
                e[k]  = xa[k] * yp[d];
                m = fmaxf(m, e[k]);
            }
            #pragma unroll
            for (int o = 16; o > 0; o >>= 1) m = fmaxf(m, __shfl_xor_sync(FULLMASK, m, o));
            float se = 0.f;
            #pragma unroll
            for (int k = 0; k < 4; k++) { e[k] = __expf(e[k] - m); se += e[k]; }
            #pragma unroll
            for (int o = 16; o > 0; o >>= 1) se += __shfl_xor_sync(FULLMASK, se, o);
            float inv = 1.f / se;
            #pragma unroll
            for (int k = 0; k < 4; k++) {
                int d = k * 32 + lane;
                sxa[tok][d] = xa[k] * (e[k] * inv);    // both warps write same values
            }
        }
        __syncwarp();       // own sxa writes visible to own cross-lane reads

        // (4) x_res update (reads own-warp sxa copies)
        {
            const int off = bi - 127;
            #pragma unroll
            for (int k = 0; k < 4; k++) {
                int d = k * 32 + lane;
                int q = d - off;
                float xe = (q >= 0 && q < 128) ? sxa[tok][q] : 0.f;
                xr[k] -= xe;
            }
        }
        PAIR_BAR(tok);      // pair-local: xp softmax-reads done before republish

        // (5) republish xp (sub1) + prefix scan (sub0) for NEXT iteration
        if (sub == 1) {
            #pragma unroll
            for (int k = 0; k < 4; k++) xp[127 + k * 32 + lane] = xr[k];
        } else {
            float run = 0.f;
            #pragma unroll
            for (int k = 0; k < 4; k++) {
                float v = xr[k] * xr[k];
                #pragma unroll
                for (int o = 1; o < 32; o <<= 1) {
                    float n = __shfl_up_sync(FULLMASK, v, o);
                    if (lane >= o) v += n;
                }
                Pp[1 + k * 32 + lane] = run + v;
                run += __shfl_sync(FULLMASK, v, 31);
            }
            if (lane == 0) Pp[0] = 0.f;
        }
        __syncthreads();   // BAR-A: sxa visible for fused MLP

        // (6) fused MLP: warp = (d-quarter mq, token pair mtp); weights loaded ONCE
        //     for both tokens; lane owns outputs lane*4..+3
        {
            const float*  wp = g_wf + (it * IDIM + mq * 32) * IDIM + lane * 4;
            const float4* h0 = (const float4*)(&sxa[2 * mtp][mq * 32]);
            const float4* h1 = (const float4*)(&sxa[2 * mtp + 1][mq * 32]);
            float c00 = 0.f, c01 = 0.f, c02 = 0.f, c03 = 0.f;
            float c10 = 0.f, c11 = 0.f, c12 = 0.f, c13 = 0.f;
            #pragma unroll 4
            for (int k4 = 0; k4 < 8; k4++) {
                float4 ha = h0[k4];                    // broadcast
                float4 hb = h1[k4];                    // broadcast
                const float* w = wp + (k4 * 4) * IDIM;
                float4 w0 = *(const float4*)(w);
                float4 w1v = *(const float4*)(w + IDIM);
                float4 w2v = *(const float4*)(w + 2 * IDIM);
                float4 w3v = *(const float4*)(w + 3 * IDIM);
                c00 = fmaf(w0.x, ha.x, c00); c01 = fmaf(w0.y, ha.x, c01);
                c02 = fmaf(w0.z, ha.x, c02); c03 = fmaf(w0.w, ha.x, c03);
                c10 = fmaf(w0.x, hb.x, c10); c11 = fmaf(w0.y, hb.x, c11);
                c12 = fmaf(w0.z, hb.x, c12); c13 = fmaf(w0.w, hb.x, c13);
                c00 = fmaf(w1v.x, ha.y, c00); c01 = fmaf(w1v.y, ha.y, c01);
                c02 = fmaf(w1v.z, ha.y, c02); c03 = fmaf(w1v.w, ha.y, c03);
                c10 = fmaf(w1v.x, hb.y, c10); c11 = fmaf(w1v.y, hb.y, c11);
                c12 = fmaf(w1v.z, hb.y, c12); c13 = fmaf(w1v.w, hb.y, c13);
                c00 = fmaf(w2v.x, ha.z, c00); c01 = fmaf(w2v.y, ha.z, c01);
                c02 = fmaf(w2v.z, ha.z, c02); c03 = fmaf(w2v.w, ha.z, c03);
                c10 = fmaf(w2v.x, hb.z, c10); c11 = fmaf(w2v.y, hb.z, c11);
                c12 = fmaf(w2v.z, hb.z, c12); c13 = fmaf(w2v.w, hb.z, c13);
                c00 = fmaf(w3v.x, ha.w, c00); c01 = fmaf(w3v.y, ha.w, c01);
                c02 = fmaf(w3v.z, ha.w, c02); c03 = fmaf(w3v.w, ha.w, c03);
                c10 = fmaf(w3v.x, hb.w, c10); c11 = fmaf(w3v.y, hb.w, c11);
                c12 = fmaf(w3v.z, hb.w, c12); c13 = fmaf(w3v.w, hb.w, c13);
            }
            *(float4*)&spart[mq][2 * mtp][lane * 4]     = make_float4(c00, c01, c02, c03);
            *(float4*)&spart[mq][2 * mtp + 1][lane * 4] = make_float4(c10, c11, c12, c13);
        }
        __syncthreads();   // BAR-C: partials visible

        // (7) warps 0-3: combine quarters (fixed order) + loss + y_res update
        if (wid < 4) {
            const int g = wid;
            float4 p0 = *(const float4*)&spart[0][g][lane * 4];
            float4 p1 = *(const float4*)&spart[1][g][lane * 4];
            float4 p2 = *(const float4*)&spart[2][g][lane * 4];
            float4 p3 = *(const float4*)&spart[3][g][lane * 4];
            float4 bfv = *(const float4*)(g_bf + it * IDIM + lane * 4);
            float4 yr  = *(const float4*)&sy[g][lane * 4];
            unsigned int mw = *(const unsigned int*)&smsk[g][lane * 4];
            float ye0 = ((p0.x + p1.x) + (p2.x + p3.x)) + bfv.x;
            float ye1 = ((p0.y + p1.y) + (p2.y + p3.y)) + bfv.y;
            float ye2 = ((p0.z + p1.z) + (p2.z + p3.z)) + bfv.z;
            float ye3 = ((p0.w + p1.w) + (p2.w + p3.w)) + bfv.w;
            float d0 = ye0 - yr.x, d1 = ye1 - yr.y, d2 = ye2 - yr.z, d3 = ye3 - yr.w;
            float k0 = (mw & 0x000000ffu) ? 0.f : 1.f;
            float k1 = (mw & 0x0000ff00u) ? 0.f : 1.f;
            float k2 = (mw & 0x00ff0000u) ? 0.f : 1.f;
            float k3 = (mw & 0xff000000u) ? 0.f : 1.f;
            lossAcc = fmaf(k0 * d0, d0, lossAcc);
            lossAcc = fmaf(k1 * d1, d1, lossAcc);
            lossAcc = fmaf(k2 * d2, d2, lossAcc);
            lossAcc = fmaf(k3 * d3, d3, lossAcc);
            *(float4*)&sy[g][lane * 4] =
                make_float4(yr.x - ye0, yr.y - ye1, yr.z - ye2, yr.w - ye3);
        }
        // loop-top BAR-TOP orders the sy writes before next-iter corr reads
    }

    // ---- deterministic per-block loss reduction ----
    for (int o = 16; o > 0; o >>= 1) lossAcc += __shfl_xor_sync(FULLMASK, lossAcc, o);
    __syncthreads();                 // protect redf reuse
    if (lane == 0) redf[wid] = lossAcc;
    __syncthreads();
    if (tid == 0) {
        float s = 0.f;
        for (int w = 0; w < 8; w++) s += redf[w];
        g_partS[blk] = s;
        __threadfence();
        unsigned int t = atomicAdd(&g_ticket, 1u);
        sIsLast = (t == NBLK - 1) ? 1 : 0;
    }
    __syncthreads();

    // ---- last block: fused deterministic finalize ----
    if (sIsLast) {
        __threadfence();
        volatile float* vS = g_partS;
        volatile int*   vC = g_partC;
        float s = vS[tid] + vS[tid + 256];      // NBLK = 512 = 2*NT
        int   c = vC[tid] + vC[tid + 256];
        for (int o = 16; o > 0; o >>= 1) {
            s += __shfl_xor_sync(FULLMASK, s, o);
            c += __shfl_xor_sync(FULLMASK, c, o);
        }
        if (lane == 0) { redf[wid] = s; redi[wid] = c; }
        __syncthreads();
        if (tid == 0) {
            float S = 0.f; int C = 0;
            for (int w = 0; w < 8; w++) { S += redf[w]; C += redi[w]; }
            out[0] = S / (4.0f * (float)C);   // mean over NIT of (sum_sq / denom)
            g_ticket = 0;                     // reset for next graph replay
        }
    }
}

extern "C" void kernel_launch(void* const* d_in, const int* in_sizes, int n_in,
                              void* d_out, int out_size)
{
    const float* x  = (const float*)d_in[0];
    const float* y  = (const float*)d_in[1];
    const float* w1 = (const float*)d_in[2];
    const float* b1 = (const float*)d_in[3];
    const float* w2 = (const float*)d_in[4];
    const float* b2 = (const float*)d_in[5];

    gemm_fuse<<<64, dim3(32, 8)>>>(w1, w2, b1, b2);
    fwd_kernel<<<NBLK, NT>>>(x, y, (float*)d_out);
}

// round 16
// speedup vs baseline: 1.2766x; 1.1115x over previous
#include <cuda_runtime.h>
#include <math.h>

#define IDIM 128
#define HDIM 1024
#define CDIM 256
#define NIT  4
#define NTOK 2048
#define G    4            // tokens per block (two warps per token)
#define NT   256          // threads per block
#define NBLK (NTOK / G)   // 512 blocks
#define IGNORE_OUT 10000.0f
#define FULLMASK 0xffffffffu

// pair-local named barrier: 64 threads (two warps of one token), ids 1..4
#define PAIR_BAR(tokid) asm volatile("bar.sync %0, 64;" :: "r"((tokid) + 1) : "memory")

// ---- device scratch (no allocations allowed) ----
__device__ float g_wf[NIT * IDIM * IDIM];  // fused W: [it][d][o], o-contiguous
__device__ float g_bf[NIT * IDIM];         // fused bias: [it][o]
__device__ float g_partS[NBLK];
__device__ int   g_partC[NBLK];
__device__ unsigned int g_ticket;          // zero-init; reset by last block each replay
__device__ unsigned int g_done;            // Wf-tile completion count; reset each replay

// ================= fused forward (includes Wf GEMM prologue on blocks 0..63) ====
__global__ __launch_bounds__(NT, 4)
void fwd_kernel(const float* __restrict__ x,  const float* __restrict__ y,
                const float* __restrict__ w1, const float* __restrict__ b1,
                const float* __restrict__ w2, const float* __restrict__ b2,
                float* __restrict__ out)
{
    __shared__ __align__(16) float sxp[G][384];       // zero-padded x_res (pad 127 each side)
    __shared__ __align__(16) float sy [G][132];       // y_res (padded)
    __shared__ __align__(16) float sxa[G][132];       // x_attn (padded)
    __shared__ __align__(16) float sP [G][132];       // prefix sums of x^2 (129 used)
    __shared__ __align__(16) float spart[4][G][132];  // MLP d-quarter partials / GEMM scratch
    __shared__ float s_bv[G][2];                      // per-warp argmax value
    __shared__ int   s_bi[G][2];                      // per-warp argmax index
    __shared__ unsigned char smsk[G][128];            // seq_mask from ORIGINAL y
    __shared__ float redf[8];
    __shared__ int   redi[8];
    __shared__ int   sIsLast;

    const int tid  = threadIdx.x;
    const int blk  = blockIdx.x;
    const int tok0 = blk * G;
    const int lane = tid & 31;
    const int wid  = tid >> 5;        // 8 warps
    const int tok  = wid >> 1;        // token for corr phases
    const int sub  = wid & 1;         // corr pass: s in [128*sub, 128*sub+128)

    // ======== Wf GEMM prologue: blocks 0..63 each compute one 32x32 tile ========
    // Wf[it][d][o] = sum_c w1[it*256+c][d] * w2[o][it*256+c]
    // bf[it][o]    = sum_c b1[it*256+c]    * w2[o][it*256+c] + b2[o]
    if (blk < 64) {
        float (*As)[33] = (float (*)[33])(&spart[0][0][0]);          // 32x33
        float (*Bs)[33] = (float (*)[33])(&spart[0][0][0] + 1056);   // 32x33
        const int it = blk >> 4;
        const int dt = (blk >> 2) & 3;
        const int ot = blk & 3;
        const int tx = tid & 31;
        const int ty = tid >> 5;      // 0..7

        float acc[4] = {0.f, 0.f, 0.f, 0.f};
        float bacc = 0.f;

        for (int kc = 0; kc < 8; kc++) {
            #pragma unroll
            for (int i = 0; i < 4; i++) {
                int c = ty + 8 * i;
                As[c][tx] = w1[(it * CDIM + kc * 32 + c) * IDIM + dt * 32 + tx];
                Bs[tx][c] = w2[(ot * 32 + c) * HDIM + it * CDIM + kc * 32 + tx];
            }
            __syncthreads();
            #pragma unroll 8
            for (int c = 0; c < 32; c++) {
                float bv = Bs[c][tx];
                #pragma unroll
                for (int i = 0; i < 4; i++)
                    acc[i] = fmaf(As[c][ty + 8 * i], bv, acc[i]);
            }
            if (dt == 0 && ty == 0) {
                #pragma unroll 8
                for (int c = 0; c < 32; c++)
                    bacc = fmaf(b1[it * CDIM + kc * 32 + c], Bs[c][tx], bacc);
            }
            __syncthreads();
        }
        #pragma unroll
        for (int i = 0; i < 4; i++)
            g_wf[(it * IDIM + dt * 32 + ty + 8 * i) * IDIM + ot * 32 + tx] = acc[i];
        if (dt == 0 && ty == 0)
            g_bf[it * IDIM + ot * 32 + tx] = bacc + b2[ot * 32 + tx];
        __threadfence();
        __syncthreads();
        if (tid == 0) atomicAdd(&g_done, 1u);
    }

    // ---- zero sxp pads + load y/mask + count ----
    for (int k = tid; k < G * 384; k += NT) sxp[k / 384][k % 384] = 0.f;

    int cnt = 0;
    #pragma unroll
    for (int q = 0; q < 2; q++) {
        int k = tid + q * NT;                 // 0..511 over (g,d)
        int g = k >> 7, d = k & 127;
        float yv = y[(tok0 + g) * IDIM + d];
        sy[g][d] = yv;
        unsigned char m = (yv == IGNORE_OUT) ? 1 : 0;
        smsk[g][d] = m;
        cnt += 1 - (int)m;
    }
    for (int o = 16; o > 0; o >>= 1) cnt += __shfl_xor_sync(FULLMASK, cnt, o);
    if (lane == 0) redi[wid] = cnt;

    // x_res registers: BOTH warps of a token pair hold identical copies.
    float xr[4];
    #pragma unroll
    for (int k = 0; k < 4; k++)
        xr[k] = x[(tok0 + tok) * IDIM + k * 32 + lane];

    __syncthreads();
    if (tid == 0) {
        int c = 0;
        for (int w = 0; w < 8; w++) c += redi[w];
        g_partC[blk] = c;
    }

    // fused-MLP mapping: warp = (d-quarter, token-pair) — weights loaded once per 2 tokens
    const int mq  = wid >> 1;              // d-quarter 0..3
    const int mtp = wid & 1;               // token pair: tokens {2*mtp, 2*mtp+1}

    // ---- prologue: publish xp + prefix sums for iteration 0 ----
    {
        float* xp = sxp[tok];
        float* Pp = sP[tok];
        if (sub == 1) {
            #pragma unroll
            for (int k = 0; k < 4; k++) xp[127 + k * 32 + lane] = xr[k];
        } else {
            float run = 0.f;
            #pragma unroll
            for (int k = 0; k < 4; k++) {
                float v = xr[k] * xr[k];
                #pragma unroll
                for (int o = 1; o < 32; o <<= 1) {
                    float n = __shfl_up_sync(FULLMASK, v, o);
                    if (lane >= o) v += n;
                }
                Pp[1 + k * 32 + lane] = run + v;
                run += __shfl_sync(FULLMASK, v, 31);
            }
            if (lane == 0) Pp[0] = 0.f;
        }
    }

    float lossAcc = 0.f;

    for (int it = 0; it < NIT; ++it) {
        __syncthreads();   // BAR-TOP: xp/sP publish + prev-iter sy visible

        float* xp = sxp[tok];
        float* Pp = sP[tok];
        float* yp = sy[tok];

        // (1) corr numerators, sliding float4 window.
        //     lane owns shifts s = 4*lane + r + 128*sub  (r = 0..3)
        float a0 = 0.f, a1 = 0.f, a2 = 0.f, a3 = 0.f;
        {
            const float4* xv = (const float4*)(xp) + lane + 32 * sub;
            const float4* yv = (const float4*)(yp);
            float4 cur = xv[0];
            #pragma unroll 8
            for (int t = 0; t < 32; t++) {
                float4 nxt = xv[t + 1];
                float4 y4  = yv[t];
                a0 = fmaf(cur.x, y4.x, a0); a0 = fmaf(cur.y, y4.y, a0);
                a0 = fmaf(cur.z, y4.z, a0); a0 = fmaf(cur.w, y4.w, a0);
                a1 = fmaf(cur.y, y4.x, a1); a1 = fmaf(cur.z, y4.y, a1);
                a1 = fmaf(cur.w, y4.z, a1); a1 = fmaf(nxt.x, y4.w, a1);
                a2 = fmaf(cur.z, y4.x, a2); a2 = fmaf(cur.w, y4.y, a2);
                a2 = fmaf(nxt.x, y4.z, a2); a2 = fmaf(nxt.y, y4.w, a2);
                a3 = fmaf(cur.w, y4.x, a3); a3 = fmaf(nxt.x, y4.y, a3);
                a3 = fmaf(nxt.y, y4.z, a3); a3 = fmaf(nxt.z, y4.w, a3);
                cur = nxt;
            }
        }

        // (2) per-warp sim + first-max argmax over its 128 shifts
        {
            const int s0 = 4 * lane + 128 * sub;
            float num[4] = {a0, a1, a2, a3};
            float bv = -INFINITY; int bi = 0;
            #pragma unroll
            for (int r = 0; r < 4; r++) {
                int s = s0 + r;
                float sim;
                if (s < 255) {
                    int lo = s - 127; if (lo < 0) lo = 0;
                    int hi = s;       if (hi > 127) hi = 127;
                    float dxv = Pp[hi + 1] - Pp[lo];
                    sim = (dxv > 0.f) ? num[r] * rsqrtf(dxv) : 0.f;
                } else sim = -INFINITY;
                if (sim > bv) { bv = sim; bi = s; }   // ascending s keeps first max
            }
            #pragma unroll
            for (int o = 16; o > 0; o >>= 1) {
                float ov = __shfl_xor_sync(FULLMASK, bv, o);
                int   oi = __shfl_xor_sync(FULLMASK, bi, o);
                if (ov > bv || (ov == bv && oi < bi)) { bv = ov; bi = oi; }
            }
            if (lane == 0) { s_bv[tok][sub] = bv; s_bi[tok][sub] = bi; }
        }
        PAIR_BAR(tok);     // pair-local: per-warp bests visible

        // (3) BOTH warps: combine, softmax attention, x_attn (redundant identical)
        int bi;
        {
            float v0 = s_bv[tok][0]; int i0 = s_bi[tok][0];
            float v1 = s_bv[tok][1]; int i1 = s_bi[tok][1];
            bi = (v1 > v0 || (v1 == v0 && i1 < i0)) ? i1 : i0;

            float xa[4], e[4];
            float m = -INFINITY;
            #pragma unroll
            for (int k = 0; k < 4; k++) {
                int d = k * 32 + lane;
                xa[k] = xp[bi + d];                    // kpt[bi][d]
                e[k]  = xa[k] * yp[d];
                m = fmaxf(m, e[k]);
            }
            #pragma unroll
            for (int o = 16; o > 0; o >>= 1) m = fmaxf(m, __shfl_xor_sync(FULLMASK, m, o));
            float se = 0.f;
            #pragma unroll
            for (int k = 0; k < 4; k++) { e[k] = __expf(e[k] - m); se += e[k]; }
            #pragma unroll
            for (int o = 16; o > 0; o >>= 1) se += __shfl_xor_sync(FULLMASK, se, o);
            float inv = 1.f / se;
            #pragma unroll
            for (int k = 0; k < 4; k++) {
                int d = k * 32 + lane;
                sxa[tok][d] = xa[k] * (e[k] * inv);    // both warps write same values
            }
        }
        __syncwarp();       // own sxa writes visible to own cross-lane reads

        // (4) x_res update (reads own-warp sxa copies)
        {
            const int off = bi - 127;
            #pragma unroll
            for (int k = 0; k < 4; k++) {
                int d = k * 32 + lane;
                int q = d - off;
                float xe = (q >= 0 && q < 128) ? sxa[tok][q] : 0.f;
                xr[k] -= xe;
            }
        }
        PAIR_BAR(tok);      // pair-local: xp softmax-reads done before republish

        // (5) republish xp (sub1) + prefix scan (sub0) for NEXT iteration
        if (sub == 1) {
            #pragma unroll
            for (int k = 0; k < 4; k++) xp[127 + k * 32 + lane] = xr[k];
        } else {
            float run = 0.f;
            #pragma unroll
            for (int k = 0; k < 4; k++) {
                float v = xr[k] * xr[k];
                #pragma unroll
                for (int o = 1; o < 32; o <<= 1) {
                    float n = __shfl_up_sync(FULLMASK, v, o);
                    if (lane >= o) v += n;
                }
                Pp[1 + k * 32 + lane] = run + v;
                run += __shfl_sync(FULLMASK, v, 31);
            }
            if (lane == 0) Pp[0] = 0.f;
        }
        __syncthreads();   // BAR-A: sxa visible for fused MLP

        // (5.5) iteration 0 only: wait for all 64 Wf tiles (overlapped with corr above)
        if (it == 0) {
            if (tid == 0) {
                while (*((volatile unsigned int*)&g_done) < 64u) { }
            }
            __syncthreads();
            __threadfence();   // acquire: order g_wf reads after flag
        }

        // (6) fused MLP: warp = (d-quarter mq, token pair mtp); weights loaded ONCE
        //     for both tokens; lane owns outputs lane*4..+3
        {
            const float*  wp = g_wf + (it * IDIM + mq * 32) * IDIM + lane * 4;
            const float4* h0 = (const float4*)(&sxa[2 * mtp][mq * 32]);
            const float4* h1 = (const float4*)(&sxa[2 * mtp + 1][mq * 32]);
            float c00 = 0.f, c01 = 0.f, c02 = 0.f, c03 = 0.f;
            float c10 = 0.f, c11 = 0.f, c12 = 0.f, c13 = 0.f;
            #pragma unroll 4
            for (int k4 = 0; k4 < 8; k4++) {
                float4 ha = h0[k4];                    // broadcast
                float4 hb = h1[k4];                    // broadcast
                const float* w = wp + (k4 * 4) * IDIM;
                float4 w0 = *(const float4*)(w);
                float4 w1v = *(const float4*)(w + IDIM);
                float4 w2v = *(const float4*)(w + 2 * IDIM);
                float4 w3v = *(const float4*)(w + 3 * IDIM);
                c00 = fmaf(w0.x, ha.x, c00); c01 = fmaf(w0.y, ha.x, c01);
                c02 = fmaf(w0.z, ha.x, c02); c03 = fmaf(w0.w, ha.x, c03);
                c10 = fmaf(w0.x, hb.x, c10); c11 = fmaf(w0.y, hb.x, c11);
                c12 = fmaf(w0.z, hb.x, c12); c13 = fmaf(w0.w, hb.x, c13);
                c00 = fmaf(w1v.x, ha.y, c00); c01 = fmaf(w1v.y, ha.y, c01);
                c02 = fmaf(w1v.z, ha.y, c02); c03 = fmaf(w1v.w, ha.y, c03);
                c10 = fmaf(w1v.x, hb.y, c10); c11 = fmaf(w1v.y, hb.y, c11);
                c12 = fmaf(w1v.z, hb.y, c12); c13 = fmaf(w1v.w, hb.y, c13);
                c00 = fmaf(w2v.x, ha.z, c00); c01 = fmaf(w2v.y, ha.z, c01);
                c02 = fmaf(w2v.z, ha.z, c02); c03 = fmaf(w2v.w, ha.z, c03);
                c10 = fmaf(w2v.x, hb.z, c10); c11 = fmaf(w2v.y, hb.z, c11);
                c12 = fmaf(w2v.z, hb.z, c12); c13 = fmaf(w2v.w, hb.z, c13);
                c00 = fmaf(w3v.x, ha.w, c00); c01 = fmaf(w3v.y, ha.w, c01);
                c02 = fmaf(w3v.z, ha.w, c02); c03 = fmaf(w3v.w, ha.w, c03);
                c10 = fmaf(w3v.x, hb.w, c10); c11 = fmaf(w3v.y, hb.w, c11);
                c12 = fmaf(w3v.z, hb.w, c12); c13 = fmaf(w3v.w, hb.w, c13);
            }
            *(float4*)&spart[mq][2 * mtp][lane * 4]     = make_float4(c00, c01, c02, c03);
            *(float4*)&spart[mq][2 * mtp + 1][lane * 4] = make_float4(c10, c11, c12, c13);
        }
        __syncthreads();   // BAR-C: partials visible

        // (7) warps 0-3: combine quarters (fixed order) + loss + y_res update
        if (wid < 4) {
            const int g = wid;
            float4 p0 = *(const float4*)&spart[0][g][lane * 4];
            float4 p1 = *(const float4*)&spart[1][g][lane * 4];
            float4 p2 = *(const float4*)&spart[2][g][lane * 4];
            float4 p3 = *(const float4*)&spart[3][g][lane * 4];
            float4 bfv = *(const float4*)(g_bf + it * IDIM + lane * 4);
            float4 yr  = *(const float4*)&sy[g][lane * 4];
            unsigned int mw = *(const unsigned int*)&smsk[g][lane * 4];
            float ye0 = ((p0.x + p1.x) + (p2.x + p3.x)) + bfv.x;
            float ye1 = ((p0.y + p1.y) + (p2.y + p3.y)) + bfv.y;
            float ye2 = ((p0.z + p1.z) + (p2.z + p3.z)) + bfv.z;
            float ye3 = ((p0.w + p1.w) + (p2.w + p3.w)) + bfv.w;
            float d0 = ye0 - yr.x, d1 = ye1 - yr.y, d2 = ye2 - yr.z, d3 = ye3 - yr.w;
            float k0 = (mw & 0x000000ffu) ? 0.f : 1.f;
            float k1 = (mw & 0x0000ff00u) ? 0.f : 1.f;
            float k2 = (mw & 0x00ff0000u) ? 0.f : 1.f;
            float k3 = (mw & 0xff000000u) ? 0.f : 1.f;
            lossAcc = fmaf(k0 * d0, d0, lossAcc);
            lossAcc = fmaf(k1 * d1, d1, lossAcc);
            lossAcc = fmaf(k2 * d2, d2, lossAcc);
            lossAcc = fmaf(k3 * d3, d3, lossAcc);
            *(float4*)&sy[g][lane * 4] =
                make_float4(yr.x - ye0, yr.y - ye1, yr.z - ye2, yr.w - ye3);
        }
        // loop-top BAR-TOP orders the sy writes before next-iter corr reads
    }

    // ---- deterministic per-block loss reduction ----
    for (int o = 16; o > 0; o >>= 1) lossAcc += __shfl_xor_sync(FULLMASK, lossAcc, o);
    __syncthreads();                 // protect redf reuse
    if (lane == 0) redf[wid] = lossAcc;
    __syncthreads();
    if (tid == 0) {
        float s = 0.f;
        for (int w = 0; w < 8; w++) s += redf[w];
        g_partS[blk] = s;
        __threadfence();
        unsigned int t = atomicAdd(&g_ticket, 1u);
        sIsLast = (t == NBLK - 1) ? 1 : 0;
    }
    __syncthreads();

    // ---- last block: fused deterministic finalize ----
    if (sIsLast) {
        __threadfence();
        volatile float* vS = g_partS;
        volatile int*   vC = g_partC;
        float s = vS[tid] + vS[tid + 256];      // NBLK = 512 = 2*NT
        int   c = vC[tid] + vC[tid + 256];
        for (int o = 16; o > 0; o >>= 1) {
            s += __shfl_xor_sync(FULLMASK, s, o);
            c += __shfl_xor_sync(FULLMASK, c, o);
        }
        if (lane == 0) { redf[wid] = s; redi[wid] = c; }
        __syncthreads();
        if (tid == 0) {
            float S = 0.f; int C = 0;
            for (int w = 0; w < 8; w++) { S += redf[w]; C += redi[w]; }
            out[0] = S / (4.0f * (float)C);   // mean over NIT of (sum_sq / denom)
            g_ticket = 0;                     // reset for next graph replay
            g_done   = 0;                     // reset Wf handshake for next replay
        }
    }
}

extern "C" void kernel_launch(void* const* d_in, const int* in_sizes, int n_in,
                              void* d_out, int out_size)
{
    const float* x  = (const float*)d_in[0];
    const float* y  = (const float*)d_in[1];
    const float* w1 = (const float*)d_in[2];
    const float* b1 = (const float*)d_in[3];
    const float* w2 = (const float*)d_in[4];
    const float* b2 = (const float*)d_in[5];

    fwd_kernel<<<NBLK, NT>>>(x, y, w1, b1, w2, b2, (float*)d_out);
}